// round 11
// baseline (speedup 1.0000x reference)
#include <cuda_runtime.h>
#include <cstdint>

// ---------------------------------------------------------------------------
// MyGraphConv: out = relu([h[:n_dst] || segment_mean(h[edge_src], edge_dst)] @ W.T + b)
//
// R11 plan:
//   stream2: prefetch_h (warm L2 for the gather) -> gemmA (g_part = h_dst @ W0.T)
//   main   : init (zero + dtype probe) -> scatter (4 edges/thr buckets)
//            -> gather (1 warp/dst, inline overflow handling, writes mean)
//            -> join -> gemmB (out = relu(g_part + mean @ W1.T + b))
//   GEMMs: Z tile stored in smem pre-packed as f32x2 broadcast pairs so the
//   inner loop is pure FFMA2 + loads (no packing movs).
// ---------------------------------------------------------------------------

#define MAX_DST 32768
#define CAP     128
#define MAX_OVF 65536
#define DIMD    128
#define OUTN    128
#define KDIM    256

__device__ int   g_cnt[MAX_DST];
__device__ int   g_csr[(size_t)MAX_DST * CAP];
__device__ int   g_ovf_n;
__device__ int   g_ovf[2 * MAX_OVF];
__device__ __align__(16) float g_mean[(size_t)MAX_DST * DIMD];
__device__ __align__(16) float g_part[(size_t)MAX_DST * OUTN];
__device__ int   g_is64;
__device__ float g_sink[1];

// --- K1: zero counters + dtype probe ------------------------------------------
__global__ void init_kernel(const void* esrc, const void* edst,
                            int E, int n_src, int n_dst) {
    __shared__ int ok;
    if (threadIdx.x == 0) ok = 1;
    __syncthreads();
    int i = blockIdx.x * blockDim.x + threadIdx.x;
    if (i < n_dst) g_cnt[i] = 0;
    if (i == 0) g_ovf_n = 0;
    if (blockIdx.x == 0 && threadIdx.x < 64) {
        int lim = E >> 1;
        if (lim < 1) {
            if (threadIdx.x == 0) atomicAnd(&ok, 0);
        } else {
            int step = (lim > 64) ? (lim / 64) : 1;
            int j = threadIdx.x * step;
            if (j < lim) {
                const unsigned long long* p = (const unsigned long long*)esrc;
                const unsigned long long* q = (const unsigned long long*)edst;
                if (p[j] >= (unsigned long long)n_src ||
                    q[j] >= (unsigned long long)n_dst)
                    atomicAnd(&ok, 0);
            }
        }
    }
    __syncthreads();
    if (blockIdx.x == 0 && threadIdx.x == 0) g_is64 = ok;
}

// --- prefetch: stream h once to make it L2-resident before gather ---------------
__global__ void prefetch_kernel(const float4* __restrict__ h4, int n4) {
    int stride = gridDim.x * blockDim.x;
    float s = 0.f;
    for (int i = blockIdx.x * blockDim.x + threadIdx.x; i < n4; i += stride) {
        float4 v = h4[i];
        s += (v.x + v.y) + (v.z + v.w);
    }
    if (__float_as_uint(s) == 0xDEADBEEFu) g_sink[0] = s;  // keep loads alive
}

// --- K2: bucket scatter, 4 edges/thread -----------------------------------------
__global__ void scatter_kernel(const void* __restrict__ esrc,
                               const void* __restrict__ edst, int E) {
    int base = (int)((blockIdx.x * (unsigned)blockDim.x + threadIdx.x) * 4u);
    bool is64 = (g_is64 != 0);
    int s[4], d[4];
#pragma unroll
    for (int j = 0; j < 4; j++) {
        int i = base + j;
        if (i < E) {
            if (is64) {
                s[j] = (int)((const long long*)esrc)[i];
                d[j] = (int)((const long long*)edst)[i];
            } else {
                s[j] = ((const int*)esrc)[i];
                d[j] = ((const int*)edst)[i];
            }
        } else d[j] = -1;
    }
    int pos[4];
#pragma unroll
    for (int j = 0; j < 4; j++)
        pos[j] = (d[j] >= 0) ? atomicAdd(&g_cnt[d[j]], 1) : 0;
#pragma unroll
    for (int j = 0; j < 4; j++) {
        if (d[j] >= 0) {
            if (pos[j] < CAP) {
                g_csr[(size_t)d[j] * CAP + pos[j]] = s[j];
            } else {
                int o = atomicAdd(&g_ovf_n, 1);
                if (o < MAX_OVF) { g_ovf[2 * o] = d[j]; g_ovf[2 * o + 1] = s[j]; }
            }
        }
    }
}

// --- K3: gather + mean (1 warp/dst, 8-way unroll, inline overflow) ---------------
__global__ void gather_kernel(const float* __restrict__ h, int n_dst) {
    int w    = (int)((blockIdx.x * (unsigned)blockDim.x + threadIdx.x) >> 5);
    int lane = threadIdx.x & 31;
    if (w >= n_dst) return;

    int cnt = g_cnt[w];
    int m = cnt < CAP ? cnt : CAP;
    const int* __restrict__ bkt = g_csr + (size_t)w * CAP;
    const float4* __restrict__ h4 = (const float4*)h;

    float4 acc = make_float4(0.f, 0.f, 0.f, 0.f);
    int i = 0;
    for (; i + 8 <= m; i += 8) {
        float4 v[8];
#pragma unroll
        for (int j = 0; j < 8; j++) {
            int s = bkt[i + j];
            v[j] = h4[(size_t)s * 32 + lane];
        }
#pragma unroll
        for (int j = 0; j < 8; j++) {
            acc.x += v[j].x; acc.y += v[j].y; acc.z += v[j].z; acc.w += v[j].w;
        }
    }
    for (; i < m; i++) {
        int s = bkt[i];
        float4 v = h4[(size_t)s * 32 + lane];
        acc.x += v.x; acc.y += v.y; acc.z += v.z; acc.w += v.w;
    }

    // Inline overflow handling (normally g_ovf_n == 0: one broadcast L2 read)
    int novf = g_ovf_n;
    if (novf > 0) {
        if (novf > MAX_OVF) novf = MAX_OVF;
        for (int e = 0; e < novf; e++) {
            if (g_ovf[2 * e] == w) {
                int s = g_ovf[2 * e + 1];
                float4 v = h4[(size_t)s * 32 + lane];
                acc.x += v.x; acc.y += v.y; acc.z += v.z; acc.w += v.w;
            }
        }
    }

    float inv = 1.0f / fmaxf((float)cnt, 1.0f);
    acc.x *= inv; acc.y *= inv; acc.z *= inv; acc.w *= inv;
    ((float4*)g_mean)[(size_t)w * 32 + lane] = acc;
}

// --- GEMM halves: 64x128 tile, K=128 each, packed f32x2, pre-packed Z -----------
#define GBM 64
#define GBN 128
#define GBK 32
#define ZS2_STRIDE 66    // ulonglong stride (8B units): 64 + 2 pad
#define WS_STRIDE  132

union F4U2 { float4 f; unsigned long long u[2]; };

#define PACK_BCAST(dst, src) \
    asm("mov.b64 %0, {%1, %1};" : "=l"(dst) : "f"(src))
#define FFMA2(acc, a2, b2) \
    asm("fma.rn.f32x2 %0, %1, %2, %0;" : "+l"(acc) : "l"(a2), "l"(b2))
#define UNPACK2(lo, hi, src) \
    asm("mov.b64 {%0, %1}, %2;" : "=f"(lo), "=f"(hi) : "l"(src))

// Zs2[k][m] holds {z,z} broadcast pairs so the inner loop has zero packing movs.
__device__ __forceinline__ void gemm_body(
    const float* __restrict__ srcZ, const float* __restrict__ W, int Wcol0,
    unsigned long long (*Zs2)[ZS2_STRIDE], float (*Ws)[WS_STRIDE],
    unsigned long long acc[4][4], int row0, int n_dst, int tid, int tx, int ty) {

    for (int kk = 0; kk < DIMD; kk += GBK) {
#pragma unroll
        for (int i = 0; i < 2; i++) {
            int f  = tid + i * 256;
            int mm = f >> 3;
            int k4 = (f & 7) * 4;
            int row = row0 + mm;
            float4 v = make_float4(0.f, 0.f, 0.f, 0.f);
            if (row < n_dst)
                v = *(const float4*)(srcZ + (size_t)row * DIMD + kk + k4);
            unsigned long long p0, p1, p2, p3;
            PACK_BCAST(p0, v.x); PACK_BCAST(p1, v.y);
            PACK_BCAST(p2, v.z); PACK_BCAST(p3, v.w);
            Zs2[k4 + 0][mm] = p0; Zs2[k4 + 1][mm] = p1;
            Zs2[k4 + 2][mm] = p2; Zs2[k4 + 3][mm] = p3;
        }
#pragma unroll
        for (int i = 0; i < 4; i++) {
            int f  = tid + i * 256;
            int nn = f >> 3;
            int k4 = (f & 7) * 4;
            float4 v = *(const float4*)(W + (size_t)nn * KDIM + Wcol0 + kk + k4);
            Ws[k4 + 0][nn] = v.x; Ws[k4 + 1][nn] = v.y;
            Ws[k4 + 2][nn] = v.z; Ws[k4 + 3][nn] = v.w;
        }
        __syncthreads();

#pragma unroll
        for (int k = 0; k < GBK; k++) {
            unsigned long long z2[4];
#pragma unroll
            for (int i = 0; i < 4; i++) z2[i] = Zs2[k][ty * 4 + i];
            F4U2 w0, w1;
            w0.f = *(const float4*)&Ws[k][tx * 8];
            w1.f = *(const float4*)&Ws[k][tx * 8 + 4];
#pragma unroll
            for (int i = 0; i < 4; i++) {
                FFMA2(acc[i][0], z2[i], w0.u[0]);
                FFMA2(acc[i][1], z2[i], w0.u[1]);
                FFMA2(acc[i][2], z2[i], w1.u[0]);
                FFMA2(acc[i][3], z2[i], w1.u[1]);
            }
        }
        __syncthreads();
    }
}

// gemmA: g_part = h_dst @ W[:, :128].T
__global__ __launch_bounds__(256, 3)
void gemmA_kernel(const float* __restrict__ h,
                  const float* __restrict__ W,
                  int n_dst) {
    __shared__ __align__(16) unsigned long long Zs2[GBK][ZS2_STRIDE];
    __shared__ __align__(16) float Ws[GBK][WS_STRIDE];
    const int tid  = threadIdx.x;
    const int tx   = tid & 15;
    const int ty   = tid >> 4;
    const int row0 = blockIdx.x * GBM;

    unsigned long long acc[4][4];
#pragma unroll
    for (int i = 0; i < 4; i++)
#pragma unroll
        for (int j = 0; j < 4; j++) acc[i][j] = 0ull;

    gemm_body(h, W, 0, Zs2, Ws, acc, row0, n_dst, tid, tx, ty);

#pragma unroll
    for (int i = 0; i < 4; i++) {
        int row = row0 + ty * 4 + i;
        if (row < n_dst) {
            float4 o0, o1;
            UNPACK2(o0.x, o0.y, acc[i][0]);
            UNPACK2(o0.z, o0.w, acc[i][1]);
            UNPACK2(o1.x, o1.y, acc[i][2]);
            UNPACK2(o1.z, o1.w, acc[i][3]);
            float* op = g_part + (size_t)row * OUTN + tx * 8;
            *(float4*)(op)     = o0;
            *(float4*)(op + 4) = o1;
        }
    }
}

// gemmB: out = relu(g_part + g_mean @ W[:, 128:].T + b)
__global__ __launch_bounds__(256, 3)
void gemmB_kernel(const float* __restrict__ W,
                  const float* __restrict__ b,
                  float* __restrict__ out,
                  int n_dst) {
    __shared__ __align__(16) unsigned long long Zs2[GBK][ZS2_STRIDE];
    __shared__ __align__(16) float Ws[GBK][WS_STRIDE];
    const int tid  = threadIdx.x;
    const int tx   = tid & 15;
    const int ty   = tid >> 4;
    const int row0 = blockIdx.x * GBM;

    unsigned long long acc[4][4];
#pragma unroll
    for (int i = 0; i < 4; i++)
#pragma unroll
        for (int j = 0; j < 4; j++) acc[i][j] = 0ull;

    gemm_body(g_mean, W, DIMD, Zs2, Ws, acc, row0, n_dst, tid, tx, ty);

    float bias[8];
#pragma unroll
    for (int j = 0; j < 8; j++) bias[j] = b[tx * 8 + j];

#pragma unroll
    for (int i = 0; i < 4; i++) {
        int row = row0 + ty * 4 + i;
        if (row < n_dst) {
            float a[8];
            UNPACK2(a[0], a[1], acc[i][0]);
            UNPACK2(a[2], a[3], acc[i][1]);
            UNPACK2(a[4], a[5], acc[i][2]);
            UNPACK2(a[6], a[7], acc[i][3]);
            const float* pp = g_part + (size_t)row * OUTN + tx * 8;
            float4 p0 = *(const float4*)(pp);
            float4 p1 = *(const float4*)(pp + 4);
            float4 o0, o1;
            o0.x = fmaxf(a[0] + p0.x + bias[0], 0.f);
            o0.y = fmaxf(a[1] + p0.y + bias[1], 0.f);
            o0.z = fmaxf(a[2] + p0.z + bias[2], 0.f);
            o0.w = fmaxf(a[3] + p0.w + bias[3], 0.f);
            o1.x = fmaxf(a[4] + p1.x + bias[4], 0.f);
            o1.y = fmaxf(a[5] + p1.y + bias[5], 0.f);
            o1.z = fmaxf(a[6] + p1.z + bias[6], 0.f);
            o1.w = fmaxf(a[7] + p1.w + bias[7], 0.f);
            float* op = out + (size_t)row * OUTN + tx * 8;
            *(float4*)(op)     = o0;
            *(float4*)(op + 4) = o1;
        }
    }
}

// ---------------------------------------------------------------------------
extern "C" void kernel_launch(void* const* d_in, const int* in_sizes, int n_in,
                              void* d_out, int out_size) {
    const float* h    = (const float*)d_in[0];
    const void*  esrc = d_in[1];
    const void*  edst = d_in[2];
    const float* W    = (const float*)d_in[3];
    const float* b    = (const float*)d_in[4];
    float*       out  = (float*)d_out;

    int n_dst = out_size / OUTN;            // 20000
    if (n_dst > MAX_DST) n_dst = MAX_DST;
    int n_src = in_sizes[0] / DIMD;         // 100000
    int E     = in_sizes[1];                // 600000

    // Fork stream: prefetch h into L2 (for gather), then gemmA.
    cudaStream_t s2 = 0;
    cudaEvent_t evFork = 0, evJoin = 0;
    bool fork_ok =
        (cudaStreamCreateWithFlags(&s2, cudaStreamNonBlocking) == cudaSuccess) &&
        (cudaEventCreateWithFlags(&evFork, cudaEventDisableTiming) == cudaSuccess) &&
        (cudaEventCreateWithFlags(&evJoin, cudaEventDisableTiming) == cudaSuccess);

    int gemm_grid = (n_dst + GBM - 1) / GBM;
    int n4 = n_src * (DIMD / 4);

    if (fork_ok) {
        cudaEventRecord(evFork, 0);
        cudaStreamWaitEvent(s2, evFork, 0);
        prefetch_kernel<<<1184, 256, 0, s2>>>((const float4*)h, n4);
        gemmA_kernel<<<gemm_grid, 256, 0, s2>>>(h, W, n_dst);
        cudaEventRecord(evJoin, s2);
    }

    // Aggregation path on the main stream
    init_kernel<<<(n_dst + 511) / 512, 512>>>(esrc, edst, E, n_src, n_dst);
    scatter_kernel<<<(E + 1023) / 1024, 256>>>(esrc, edst, E);
    gather_kernel<<<(n_dst * 32 + 255) / 256, 256>>>(h, n_dst);

    if (fork_ok) {
        cudaStreamWaitEvent((cudaStream_t)0, evJoin, 0);
    } else {
        prefetch_kernel<<<1184, 256>>>((const float4*)h, n4);
        gemmA_kernel<<<gemm_grid, 256>>>(h, W, n_dst);
    }

    gemmB_kernel<<<gemm_grid, 256>>>(W, b, out, n_dst);
}

// round 12
// speedup vs baseline: 1.0270x; 1.0270x over previous
#include <cuda_runtime.h>
#include <cstdint>

// ---------------------------------------------------------------------------
// MyGraphConv: out = relu([h[:n_dst] || segment_mean(h[edge_src], edge_dst)] @ W.T + b)
//
// R11 plan:
//   stream2: prefetch_h (warm L2 for the gather) -> gemmA (g_part = h_dst @ W0.T)
//   main   : init (zero + dtype probe) -> scatter (4 edges/thr buckets)
//            -> gather (1 warp/dst, inline overflow handling, writes mean)
//            -> join -> gemmB (out = relu(g_part + mean @ W1.T + b))
//   GEMMs: Z tile stored in smem pre-packed as f32x2 broadcast pairs so the
//   inner loop is pure FFMA2 + loads (no packing movs).
// ---------------------------------------------------------------------------

#define MAX_DST 32768
#define CAP     128
#define MAX_OVF 65536
#define DIMD    128
#define OUTN    128
#define KDIM    256

__device__ int   g_cnt[MAX_DST];
__device__ int   g_csr[(size_t)MAX_DST * CAP];
__device__ int   g_ovf_n;
__device__ int   g_ovf[2 * MAX_OVF];
__device__ __align__(16) float g_mean[(size_t)MAX_DST * DIMD];
__device__ __align__(16) float g_part[(size_t)MAX_DST * OUTN];
__device__ int   g_is64;
__device__ float g_sink[1];

// --- K1: zero counters + dtype probe ------------------------------------------
__global__ void init_kernel(const void* esrc, const void* edst,
                            int E, int n_src, int n_dst) {
    __shared__ int ok;
    if (threadIdx.x == 0) ok = 1;
    __syncthreads();
    int i = blockIdx.x * blockDim.x + threadIdx.x;
    if (i < n_dst) g_cnt[i] = 0;
    if (i == 0) g_ovf_n = 0;
    if (blockIdx.x == 0 && threadIdx.x < 64) {
        int lim = E >> 1;
        if (lim < 1) {
            if (threadIdx.x == 0) atomicAnd(&ok, 0);
        } else {
            int step = (lim > 64) ? (lim / 64) : 1;
            int j = threadIdx.x * step;
            if (j < lim) {
                const unsigned long long* p = (const unsigned long long*)esrc;
                const unsigned long long* q = (const unsigned long long*)edst;
                if (p[j] >= (unsigned long long)n_src ||
                    q[j] >= (unsigned long long)n_dst)
                    atomicAnd(&ok, 0);
            }
        }
    }
    __syncthreads();
    if (blockIdx.x == 0 && threadIdx.x == 0) g_is64 = ok;
}

// --- prefetch: stream h once to make it L2-resident before gather ---------------
__global__ void prefetch_kernel(const float4* __restrict__ h4, int n4) {
    int stride = gridDim.x * blockDim.x;
    float s = 0.f;
    for (int i = blockIdx.x * blockDim.x + threadIdx.x; i < n4; i += stride) {
        float4 v = h4[i];
        s += (v.x + v.y) + (v.z + v.w);
    }
    if (__float_as_uint(s) == 0xDEADBEEFu) g_sink[0] = s;  // keep loads alive
}

// --- K2: bucket scatter, 4 edges/thread -----------------------------------------
__global__ void scatter_kernel(const void* __restrict__ esrc,
                               const void* __restrict__ edst, int E) {
    int base = (int)((blockIdx.x * (unsigned)blockDim.x + threadIdx.x) * 4u);
    bool is64 = (g_is64 != 0);
    int s[4], d[4];
#pragma unroll
    for (int j = 0; j < 4; j++) {
        int i = base + j;
        if (i < E) {
            if (is64) {
                s[j] = (int)((const long long*)esrc)[i];
                d[j] = (int)((const long long*)edst)[i];
            } else {
                s[j] = ((const int*)esrc)[i];
                d[j] = ((const int*)edst)[i];
            }
        } else d[j] = -1;
    }
    int pos[4];
#pragma unroll
    for (int j = 0; j < 4; j++)
        pos[j] = (d[j] >= 0) ? atomicAdd(&g_cnt[d[j]], 1) : 0;
#pragma unroll
    for (int j = 0; j < 4; j++) {
        if (d[j] >= 0) {
            if (pos[j] < CAP) {
                g_csr[(size_t)d[j] * CAP + pos[j]] = s[j];
            } else {
                int o = atomicAdd(&g_ovf_n, 1);
                if (o < MAX_OVF) { g_ovf[2 * o] = d[j]; g_ovf[2 * o + 1] = s[j]; }
            }
        }
    }
}

// --- K3: gather + mean (1 warp/dst, 8-way unroll, inline overflow) ---------------
__global__ void gather_kernel(const float* __restrict__ h, int n_dst) {
    int w    = (int)((blockIdx.x * (unsigned)blockDim.x + threadIdx.x) >> 5);
    int lane = threadIdx.x & 31;
    if (w >= n_dst) return;

    int cnt = g_cnt[w];
    int m = cnt < CAP ? cnt : CAP;
    const int* __restrict__ bkt = g_csr + (size_t)w * CAP;
    const float4* __restrict__ h4 = (const float4*)h;

    float4 acc = make_float4(0.f, 0.f, 0.f, 0.f);
    int i = 0;
    for (; i + 8 <= m; i += 8) {
        float4 v[8];
#pragma unroll
        for (int j = 0; j < 8; j++) {
            int s = bkt[i + j];
            v[j] = h4[(size_t)s * 32 + lane];
        }
#pragma unroll
        for (int j = 0; j < 8; j++) {
            acc.x += v[j].x; acc.y += v[j].y; acc.z += v[j].z; acc.w += v[j].w;
        }
    }
    for (; i < m; i++) {
        int s = bkt[i];
        float4 v = h4[(size_t)s * 32 + lane];
        acc.x += v.x; acc.y += v.y; acc.z += v.z; acc.w += v.w;
    }

    // Inline overflow handling (normally g_ovf_n == 0: one broadcast L2 read)
    int novf = g_ovf_n;
    if (novf > 0) {
        if (novf > MAX_OVF) novf = MAX_OVF;
        for (int e = 0; e < novf; e++) {
            if (g_ovf[2 * e] == w) {
                int s = g_ovf[2 * e + 1];
                float4 v = h4[(size_t)s * 32 + lane];
                acc.x += v.x; acc.y += v.y; acc.z += v.z; acc.w += v.w;
            }
        }
    }

    float inv = 1.0f / fmaxf((float)cnt, 1.0f);
    acc.x *= inv; acc.y *= inv; acc.z *= inv; acc.w *= inv;
    ((float4*)g_mean)[(size_t)w * 32 + lane] = acc;
}

// --- GEMM halves: 64x128 tile, K=128 each, packed f32x2, pre-packed Z -----------
#define GBM 64
#define GBN 128
#define GBK 32
#define ZS2_STRIDE 66    // ulonglong stride (8B units): 64 + 2 pad
#define WS_STRIDE  132

union F4U2 { float4 f; unsigned long long u[2]; };

#define PACK_BCAST(dst, src) \
    asm("mov.b64 %0, {%1, %1};" : "=l"(dst) : "f"(src))
#define FFMA2(acc, a2, b2) \
    asm("fma.rn.f32x2 %0, %1, %2, %0;" : "+l"(acc) : "l"(a2), "l"(b2))
#define UNPACK2(lo, hi, src) \
    asm("mov.b64 {%0, %1}, %2;" : "=f"(lo), "=f"(hi) : "l"(src))

// Zs2[k][m] holds {z,z} broadcast pairs so the inner loop has zero packing movs.
__device__ __forceinline__ void gemm_body(
    const float* __restrict__ srcZ, const float* __restrict__ W, int Wcol0,
    unsigned long long (*Zs2)[ZS2_STRIDE], float (*Ws)[WS_STRIDE],
    unsigned long long acc[4][4], int row0, int n_dst, int tid, int tx, int ty) {

    for (int kk = 0; kk < DIMD; kk += GBK) {
#pragma unroll
        for (int i = 0; i < 2; i++) {
            int f  = tid + i * 256;
            int mm = f >> 3;
            int k4 = (f & 7) * 4;
            int row = row0 + mm;
            float4 v = make_float4(0.f, 0.f, 0.f, 0.f);
            if (row < n_dst)
                v = *(const float4*)(srcZ + (size_t)row * DIMD + kk + k4);
            unsigned long long p0, p1, p2, p3;
            PACK_BCAST(p0, v.x); PACK_BCAST(p1, v.y);
            PACK_BCAST(p2, v.z); PACK_BCAST(p3, v.w);
            Zs2[k4 + 0][mm] = p0; Zs2[k4 + 1][mm] = p1;
            Zs2[k4 + 2][mm] = p2; Zs2[k4 + 3][mm] = p3;
        }
#pragma unroll
        for (int i = 0; i < 4; i++) {
            int f  = tid + i * 256;
            int nn = f >> 3;
            int k4 = (f & 7) * 4;
            float4 v = *(const float4*)(W + (size_t)nn * KDIM + Wcol0 + kk + k4);
            Ws[k4 + 0][nn] = v.x; Ws[k4 + 1][nn] = v.y;
            Ws[k4 + 2][nn] = v.z; Ws[k4 + 3][nn] = v.w;
        }
        __syncthreads();

#pragma unroll
        for (int k = 0; k < GBK; k++) {
            unsigned long long z2[4];
#pragma unroll
            for (int i = 0; i < 4; i++) z2[i] = Zs2[k][ty * 4 + i];
            F4U2 w0, w1;
            w0.f = *(const float4*)&Ws[k][tx * 8];
            w1.f = *(const float4*)&Ws[k][tx * 8 + 4];
#pragma unroll
            for (int i = 0; i < 4; i++) {
                FFMA2(acc[i][0], z2[i], w0.u[0]);
                FFMA2(acc[i][1], z2[i], w0.u[1]);
                FFMA2(acc[i][2], z2[i], w1.u[0]);
                FFMA2(acc[i][3], z2[i], w1.u[1]);
            }
        }
        __syncthreads();
    }
}

// gemmA: g_part = h_dst @ W[:, :128].T
__global__ __launch_bounds__(256, 3)
void gemmA_kernel(const float* __restrict__ h,
                  const float* __restrict__ W,
                  int n_dst) {
    __shared__ __align__(16) unsigned long long Zs2[GBK][ZS2_STRIDE];
    __shared__ __align__(16) float Ws[GBK][WS_STRIDE];
    const int tid  = threadIdx.x;
    const int tx   = tid & 15;
    const int ty   = tid >> 4;
    const int row0 = blockIdx.x * GBM;

    unsigned long long acc[4][4];
#pragma unroll
    for (int i = 0; i < 4; i++)
#pragma unroll
        for (int j = 0; j < 4; j++) acc[i][j] = 0ull;

    gemm_body(h, W, 0, Zs2, Ws, acc, row0, n_dst, tid, tx, ty);

#pragma unroll
    for (int i = 0; i < 4; i++) {
        int row = row0 + ty * 4 + i;
        if (row < n_dst) {
            float4 o0, o1;
            UNPACK2(o0.x, o0.y, acc[i][0]);
            UNPACK2(o0.z, o0.w, acc[i][1]);
            UNPACK2(o1.x, o1.y, acc[i][2]);
            UNPACK2(o1.z, o1.w, acc[i][3]);
            float* op = g_part + (size_t)row * OUTN + tx * 8;
            *(float4*)(op)     = o0;
            *(float4*)(op + 4) = o1;
        }
    }
}

// gemmB: out = relu(g_part + g_mean @ W[:, 128:].T + b)
__global__ __launch_bounds__(256, 3)
void gemmB_kernel(const float* __restrict__ W,
                  const float* __restrict__ b,
                  float* __restrict__ out,
                  int n_dst) {
    __shared__ __align__(16) unsigned long long Zs2[GBK][ZS2_STRIDE];
    __shared__ __align__(16) float Ws[GBK][WS_STRIDE];
    const int tid  = threadIdx.x;
    const int tx   = tid & 15;
    const int ty   = tid >> 4;
    const int row0 = blockIdx.x * GBM;

    unsigned long long acc[4][4];
#pragma unroll
    for (int i = 0; i < 4; i++)
#pragma unroll
        for (int j = 0; j < 4; j++) acc[i][j] = 0ull;

    gemm_body(g_mean, W, DIMD, Zs2, Ws, acc, row0, n_dst, tid, tx, ty);

    float bias[8];
#pragma unroll
    for (int j = 0; j < 8; j++) bias[j] = b[tx * 8 + j];

#pragma unroll
    for (int i = 0; i < 4; i++) {
        int row = row0 + ty * 4 + i;
        if (row < n_dst) {
            float a[8];
            UNPACK2(a[0], a[1], acc[i][0]);
            UNPACK2(a[2], a[3], acc[i][1]);
            UNPACK2(a[4], a[5], acc[i][2]);
            UNPACK2(a[6], a[7], acc[i][3]);
            const float* pp = g_part + (size_t)row * OUTN + tx * 8;
            float4 p0 = *(const float4*)(pp);
            float4 p1 = *(const float4*)(pp + 4);
            float4 o0, o1;
            o0.x = fmaxf(a[0] + p0.x + bias[0], 0.f);
            o0.y = fmaxf(a[1] + p0.y + bias[1], 0.f);
            o0.z = fmaxf(a[2] + p0.z + bias[2], 0.f);
            o0.w = fmaxf(a[3] + p0.w + bias[3], 0.f);
            o1.x = fmaxf(a[4] + p1.x + bias[4], 0.f);
            o1.y = fmaxf(a[5] + p1.y + bias[5], 0.f);
            o1.z = fmaxf(a[6] + p1.z + bias[6], 0.f);
            o1.w = fmaxf(a[7] + p1.w + bias[7], 0.f);
            float* op = out + (size_t)row * OUTN + tx * 8;
            *(float4*)(op)     = o0;
            *(float4*)(op + 4) = o1;
        }
    }
}

// ---------------------------------------------------------------------------
extern "C" void kernel_launch(void* const* d_in, const int* in_sizes, int n_in,
                              void* d_out, int out_size) {
    const float* h    = (const float*)d_in[0];
    const void*  esrc = d_in[1];
    const void*  edst = d_in[2];
    const float* W    = (const float*)d_in[3];
    const float* b    = (const float*)d_in[4];
    float*       out  = (float*)d_out;

    int n_dst = out_size / OUTN;            // 20000
    if (n_dst > MAX_DST) n_dst = MAX_DST;
    int n_src = in_sizes[0] / DIMD;         // 100000
    int E     = in_sizes[1];                // 600000

    // Fork stream: prefetch h into L2 (for gather), then gemmA.
    cudaStream_t s2 = 0;
    cudaEvent_t evFork = 0, evJoin = 0;
    bool fork_ok =
        (cudaStreamCreateWithFlags(&s2, cudaStreamNonBlocking) == cudaSuccess) &&
        (cudaEventCreateWithFlags(&evFork, cudaEventDisableTiming) == cudaSuccess) &&
        (cudaEventCreateWithFlags(&evJoin, cudaEventDisableTiming) == cudaSuccess);

    int gemm_grid = (n_dst + GBM - 1) / GBM;
    int n4 = n_src * (DIMD / 4);

    if (fork_ok) {
        cudaEventRecord(evFork, 0);
        cudaStreamWaitEvent(s2, evFork, 0);
        prefetch_kernel<<<1184, 256, 0, s2>>>((const float4*)h, n4);
        gemmA_kernel<<<gemm_grid, 256, 0, s2>>>(h, W, n_dst);
        cudaEventRecord(evJoin, s2);
    }

    // Aggregation path on the main stream
    init_kernel<<<(n_dst + 511) / 512, 512>>>(esrc, edst, E, n_src, n_dst);
    scatter_kernel<<<(E + 1023) / 1024, 256>>>(esrc, edst, E);
    gather_kernel<<<(n_dst * 32 + 255) / 256, 256>>>(h, n_dst);

    if (fork_ok) {
        cudaStreamWaitEvent((cudaStream_t)0, evJoin, 0);
    } else {
        prefetch_kernel<<<1184, 256>>>((const float4*)h, n4);
        gemmA_kernel<<<gemm_grid, 256>>>(h, W, n_dst);
    }

    gemmB_kernel<<<gemm_grid, 256>>>(W, b, out, n_dst);
}